// round 4
// baseline (speedup 1.0000x reference)
#include <cuda_runtime.h>
#include <cstdint>

typedef unsigned long long ull;

// Problem constants
#define N_  16
#define T_  4096
#define I_  256
#define H_  512
#define C_  128     // number of chunks
#define L_  32      // chunk length, C_*L_ == T_

// packed f32x2 FMA (used only in bscan)
#define FMA2(d,a,b,c) asm("fma.rn.f32x2 %0, %1, %2, %3;" : "=l"(d) : "l"(a), "l"(b), "l"(c))

__device__ __forceinline__ float2 unpack2(ull v) {
    float2 r;
    asm("mov.b64 {%0,%1}, %2;" : "=f"(r.x), "=f"(r.y) : "l"(v));
    return r;
}
__device__ __forceinline__ ull cat2(unsigned lo, unsigned hi) {
    return (ull)lo | ((ull)hi << 32);
}

// -------- static device scratch (no allocation allowed) --------
__device__ float g_Wp  [H_*H_];   // packed scan weights: Wp[(k4*H+j)*4+r] = Whh[j*H + k4*4+r]
__device__ float g_Wit [I_*H_];   // Wi^T : Wit[i*H+j] = Wi[j*I+i]
__device__ float g_P0  [H_*H_];   // squaring ping  (Whh^2k, row-major)
__device__ float g_P1  [H_*H_];   // squaring pong
__device__ float g_lend[C_*N_*H_]; // local state at each chunk end
__device__ float g_hb  [C_*N_*H_]; // true hidden at each chunk end

// monotonic grid barrier state (never reset -> deterministic across graph replays)
__device__ unsigned g_cnt = 0;
__device__ unsigned g_rel = 0;

__device__ __forceinline__ void grid_barrier_dev(unsigned total)
{
    __syncthreads();
    if (threadIdx.x == 0) {
        __threadfence();
        unsigned my = atomicAdd(&g_cnt, 1u);
        if ((my % total) == total - 1u) {
            atomicAdd(&g_rel, 1u);
        } else {
            unsigned need = my / total + 1u;
            while (*((volatile unsigned*)&g_rel) < need) { }
        }
    }
    __syncthreads();
}

// -------- K0: build Wp (packed scan weights) and Wit (Wi transpose) --------
__global__ void k_prep(const float* __restrict__ Whh, const float* __restrict__ Wi)
{
    int idx = blockIdx.x * blockDim.x + threadIdx.x;   // over H*H
    if (idx < H_*H_) {
        int j = idx / H_, k = idx % H_;
        float v = Whh[idx];                 // Whh[j][k]
        g_Wp[((k >> 2)*H_ + j)*4 + (k & 3)] = v;
    }
    if (idx < H_*I_) {
        int j = idx / I_, i = idx % I_;
        g_Wit[i*H_ + j] = Wi[idx];
    }
}

// ---------------------------------------------------------------------------
// gemm_k: C = A[M,K] @ B[K,Nn]   (both row-major, C pitch = Nn)
// tile 128m x 64n, BK=16, 256 threads, per-thread 8m x 4n scalar FFMA.
// MODE 0: plain store (matrix squaring)
// MODE 1: RNN projection epilogue (q shift + bias + initial)
// ---------------------------------------------------------------------------
template<int MODE>
__global__ void __launch_bounds__(256, 2)
gemm_k(const float* __restrict__ A, const float* __restrict__ B,
       float* __restrict__ Cc, int M, int K, int Nn,
       const float* __restrict__ bias, const float* __restrict__ initial)
{
    __shared__ __align__(16) float As[16][136];  // [k][m]
    __shared__ __align__(16) float Bs[16][64];   // [k][n]

    const int tid = threadIdx.x;
    const int bm = blockIdx.y * 128;
    const int bn = blockIdx.x * 64;
    const int tx = tid & 15;        // n group: bn + tx*4
    const int ty = tid >> 4;        // m group: bm + ty*8

    const int arow = tid >> 1;
    const int akof = (tid & 1) * 8;
    const int brow = tid >> 4;
    const int bcol = (tid & 15) * 4;

    float acc[8][4];
#pragma unroll
    for (int i = 0; i < 8; ++i)
#pragma unroll
        for (int jj = 0; jj < 4; ++jj) acc[i][jj] = 0.f;

    for (int kt = 0; kt < K; kt += 16) {
        const float* Ab = A + (size_t)(bm + arow) * K + kt + akof;
        float4 a0 = *(const float4*)&Ab[0];
        float4 a1 = *(const float4*)&Ab[4];
        As[akof+0][arow] = a0.x; As[akof+1][arow] = a0.y;
        As[akof+2][arow] = a0.z; As[akof+3][arow] = a0.w;
        As[akof+4][arow] = a1.x; As[akof+5][arow] = a1.y;
        As[akof+6][arow] = a1.z; As[akof+7][arow] = a1.w;
        *(float4*)&Bs[brow][bcol] = *(const float4*)&B[(size_t)(kt + brow) * Nn + bn + bcol];
        __syncthreads();

#pragma unroll
        for (int k = 0; k < 16; ++k) {
            float4 av0 = *(const float4*)&As[k][ty*8];
            float4 av1 = *(const float4*)&As[k][ty*8 + 4];
            float4 bv  = *(const float4*)&Bs[k][tx*4];
            float am[8] = {av0.x,av0.y,av0.z,av0.w, av1.x,av1.y,av1.z,av1.w};
            float bb[4] = {bv.x,bv.y,bv.z,bv.w};
#pragma unroll
            for (int i = 0; i < 8; ++i)
#pragma unroll
                for (int jj = 0; jj < 4; ++jj)
                    acc[i][jj] = fmaf(am[i], bb[jj], acc[i][jj]);
        }
        __syncthreads();
    }

    if (MODE == 0) {
#pragma unroll
        for (int i = 0; i < 8; ++i) {
            int m = bm + ty*8 + i;
            *(float4*)&Cc[(size_t)m * Nn + bn + tx*4]
                = make_float4(acc[i][0], acc[i][1], acc[i][2], acc[i][3]);
        }
    } else {
        float4 bv = *(const float4*)&bias[bn + tx*4];
#pragma unroll
        for (int i = 0; i < 8; ++i) {
            int r = bm + ty*8 + i;
            int s = r & (T_ - 1);
            int n = r >> 12;
            float4 v = make_float4(acc[i][0]+bv.x, acc[i][1]+bv.y,
                                   acc[i][2]+bv.z, acc[i][3]+bv.w);
            if (s < T_ - 1)
                *(float4*)&Cc[((size_t)n*T_ + s + 1)*H_ + bn + tx*4] = v;
            if (s == 0) {
                float4 iv = *(const float4*)&initial[(size_t)n*H_ + bn + tx*4];
                *(float4*)&Cc[((size_t)n*T_)*H_ + bn + tx*4]
                    = make_float4(v.x+iv.x, v.y+iv.y, v.z+iv.z, v.w+iv.w);
            }
        }
    }
}

// -------- K2: local scan per chunk (carry-in = 0), in place over q --------
// Scalar FFMA, packed Wp loads (1x LDG.128 per 4 k), hs reads are warp-broadcast.
__global__ void __launch_bounds__(512, 1)
k_local(const float* __restrict__ Wp, float* __restrict__ q, float* __restrict__ lend)
{
    __shared__ __align__(16) float hs[N_][H_];   // [n][k]
    const int c = blockIdx.x;
    const int j = threadIdx.x;
    const int t0 = c * L_;

#pragma unroll
    for (int n = 0; n < N_; ++n)
        hs[n][j] = q[((size_t)n*T_ + t0)*H_ + j];
    __syncthreads();

    for (int s = 1; s < L_; ++s) {
        const size_t t = (size_t)t0 + s;
        float acc[N_];
#pragma unroll
        for (int n = 0; n < N_; ++n)
            acc[n] = q[((size_t)n*T_ + t)*H_ + j];

#pragma unroll 2
        for (int k4 = 0; k4 < H_/4; ++k4) {
            float4 w = *(const float4*)&Wp[((size_t)k4*H_ + j)*4];
#pragma unroll
            for (int n = 0; n < N_; ++n) {
                float4 h = *(const float4*)&hs[n][k4*4];
                acc[n] = fmaf(h.x, w.x, acc[n]);
                acc[n] = fmaf(h.y, w.y, acc[n]);
                acc[n] = fmaf(h.z, w.z, acc[n]);
                acc[n] = fmaf(h.w, w.w, acc[n]);
            }
        }
        __syncthreads();
#pragma unroll
        for (int n = 0; n < N_; ++n) {
            hs[n][j] = acc[n];
            q[((size_t)n*T_ + t)*H_ + j] = acc[n];
        }
        __syncthreads();
    }
#pragma unroll
    for (int n = 0; n < N_; ++n)
        lend[((size_t)c*N_ + n)*H_ + j] = hs[n][j];
}

// -------- K4: boundary scan (persistent, grid barrier) --------
// hb[0] = lend[0];  hb[c][n][j] = sum_k WL[j][k]*hb[c-1][n][k] + lend[c][n][j]
__global__ void __launch_bounds__(256, 1)
k_bscan(const float* __restrict__ WL, const float* __restrict__ lend, float* __restrict__ hb)
{
    const int b   = blockIdx.x;            // 0..31
    const int tid = threadIdx.x;
    const unsigned total = gridDim.x;      // 32
    const int n = tid >> 4;                // 0..15
    const int j = b * 16 + (tid & 15);     // 0..511

    {
        int idx = b * 256 + tid;           // 32*256 = 8192 = N*H
        __stcg(&hb[idx], lend[idx]);
    }
    grid_barrier_dev(total);

    const float* wrow = WL + (size_t)j * H_;   // L1-resident across steps
    for (int c = 1; c < C_; ++c) {
        const float* hrow = hb + (size_t)(c-1)*N_*H_ + (size_t)n*H_;
        ull a0 = 0ull, a1 = 0ull;
#pragma unroll 8
        for (int k4 = 0; k4 < H_/4; ++k4) {
            uint4 hu = __ldcg((const uint4*)&hrow[k4*4]);     // peer-CTA data: L2 path
            ulonglong2 w = *(const ulonglong2*)&wrow[k4*4];
            ull h01 = cat2(hu.x, hu.y);
            ull h23 = cat2(hu.z, hu.w);
            if (k4 & 1) { FMA2(a1, h01, w.x, a1); FMA2(a1, h23, w.y, a1); }
            else        { FMA2(a0, h01, w.x, a0); FMA2(a0, h23, w.y, a0); }
        }
        float2 f0 = unpack2(a0), f1 = unpack2(a1);
        float acc = lend[(size_t)c*N_*H_ + (size_t)n*H_ + j] + ((f0.x+f0.y) + (f1.x+f1.y));
        __stcg(&hb[(size_t)c*N_*H_ + (size_t)n*H_ + j], acc);
        grid_barrier_dev(total);
    }
}

// -------- K5: correction pass per chunk; finalize out0 (+ duplicate to out1) --------
__global__ void __launch_bounds__(512, 1)
k_corr(const float* __restrict__ Wp, const float* __restrict__ hb,
       float* __restrict__ out0, float* __restrict__ out1, int dup)
{
    const int c = blockIdx.x;
    const int j = threadIdx.x;

    if (c == 0) {   // chunk 0: local state IS the answer; just mirror to out1
        if (dup) {
            for (int s = 0; s < L_; ++s) {
#pragma unroll
                for (int n = 0; n < N_; ++n) {
                    size_t idx = ((size_t)n*T_ + s)*H_ + j;
                    out1[idx] = out0[idx];
                }
            }
        }
        return;
    }

    __shared__ __align__(16) float ds[N_][H_];
    const int t0 = c * L_;
#pragma unroll
    for (int n = 0; n < N_; ++n)
        ds[n][j] = hb[((size_t)(c-1)*N_ + n)*H_ + j];
    __syncthreads();

    for (int s = 0; s < L_; ++s) {
        const size_t t = (size_t)t0 + s;
        float acc[N_];
#pragma unroll
        for (int n = 0; n < N_; ++n) acc[n] = 0.f;

#pragma unroll 2
        for (int k4 = 0; k4 < H_/4; ++k4) {
            float4 w = *(const float4*)&Wp[((size_t)k4*H_ + j)*4];
#pragma unroll
            for (int n = 0; n < N_; ++n) {
                float4 h = *(const float4*)&ds[n][k4*4];
                acc[n] = fmaf(h.x, w.x, acc[n]);
                acc[n] = fmaf(h.y, w.y, acc[n]);
                acc[n] = fmaf(h.z, w.z, acc[n]);
                acc[n] = fmaf(h.w, w.w, acc[n]);
            }
        }
        __syncthreads();
#pragma unroll
        for (int n = 0; n < N_; ++n) {
            ds[n][j] = acc[n];
            size_t idx = ((size_t)n*T_ + t)*H_ + j;
            float v = out0[idx] + acc[n];
            out0[idx] = v;
            if (dup) out1[idx] = v;
        }
        __syncthreads();
    }
}

// ----------------------------------------------------------------------------
extern "C" void kernel_launch(void* const* d_in, const int* in_sizes, int n_in,
                              void* d_out, int out_size)
{
    const float *x = nullptr, *initial = nullptr, *Wi = nullptr, *bi = nullptr, *Whh = nullptr;
    for (int i = 0; i < n_in; ++i) {
        switch (in_sizes[i]) {
            case N_*T_*I_: x       = (const float*)d_in[i]; break;
            case N_*H_:    initial = (const float*)d_in[i]; break;
            case H_*I_:    Wi      = (const float*)d_in[i]; break;
            case H_:       bi      = (const float*)d_in[i]; break;
            case H_*H_:    Whh     = (const float*)d_in[i]; break;
        }
    }
    if (!x       && n_in > 0) x       = (const float*)d_in[0];
    if (!initial && n_in > 1) initial = (const float*)d_in[1];
    if (!Wi      && n_in > 2) Wi      = (const float*)d_in[2];
    if (!bi      && n_in > 3) bi      = (const float*)d_in[3];
    if (!Whh     && n_in > 4) Whh     = (const float*)d_in[4];

    float* out0 = (float*)d_out;
    const size_t NTH = (size_t)N_ * T_ * H_;
    int dup = ((size_t)out_size >= 2 * NTH) ? 1 : 0;
    float* out1 = out0 + NTH;

    float *Wp, *Wit, *P0, *P1, *lend, *hb;
    cudaGetSymbolAddress((void**)&Wp,   g_Wp);
    cudaGetSymbolAddress((void**)&Wit,  g_Wit);
    cudaGetSymbolAddress((void**)&P0,   g_P0);
    cudaGetSymbolAddress((void**)&P1,   g_P1);
    cudaGetSymbolAddress((void**)&lend, g_lend);
    cudaGetSymbolAddress((void**)&hb,   g_hb);

    dim3 gs(H_/64, H_/128);        // squaring grid (8, 4)

    // Launch #1: weight layouts
    k_prep<<<(H_*H_ + 255)/256, 256>>>(Whh, Wi);

    // Launch #2: projection q into out0:  q = x @ Wit
    {
        dim3 g(H_/64, (N_*T_)/128);   // (8, 512)
        gemm_k<1><<<g, 256>>>(x, Wit, out0, N_*T_, I_, H_, bi, initial);
    }

    // Launches #3-5: first three squarings (Whh^2, ^4, ^8)
    gemm_k<0><<<gs, 256>>>(Whh, Whh, P0, H_, H_, H_, nullptr, nullptr); // ^2
    gemm_k<0><<<gs, 256>>>(P0,  P0,  P1, H_, H_, H_, nullptr, nullptr); // ^4
    gemm_k<0><<<gs, 256>>>(P1,  P1,  P0, H_, H_, H_, nullptr, nullptr); // ^8

    // Launch #6 (ncu -s 5 -c 1 profiles THIS one): local scan
    k_local<<<C_, 512>>>(Wp, out0, lend);

    // Launches #7-8: remaining squarings (^16, ^32)
    gemm_k<0><<<gs, 256>>>(P0,  P0,  P1, H_, H_, H_, nullptr, nullptr); // ^16
    gemm_k<0><<<gs, 256>>>(P1,  P1,  P0, H_, H_, H_, nullptr, nullptr); // ^32

    // Launch #9: boundary scan (persistent kernel, 32 CTAs, grid barrier)
    k_bscan<<<32, 256>>>(P0, lend, hb);

    // Launch #10: correction + finalize (+ duplicate output)
    k_corr<<<C_, 512>>>(Wp, hb, out0, out1, dup);
}

// round 5
// speedup vs baseline: 1.2420x; 1.2420x over previous
#include <cuda_runtime.h>
#include <cstdint>

// Problem constants
#define N_  16
#define T_  4096
#define I_  256
#define H_  512
#define C_  128     // number of chunks
#define L_  32      // chunk length, C_*L_ == T_

// -------- static device scratch (no allocation allowed) --------
__device__ float g_Wt [H_*H_];   // S = Whh^T row-major: Wt[k*H+j] = Whh[j*H+k]
__device__ float g_Wit[I_*H_];   // Wi^T : Wit[i*H+j] = Wi[j*I+i]
__device__ float g_P0 [H_*H_];   // squaring ping  (S^2k row-major)
__device__ float g_P1 [H_*H_];   // squaring pong
__device__ float g_lend[C_*N_*H_]; // local state at each chunk end
__device__ float g_hb  [C_*N_*H_]; // true hidden at each chunk end

// monotonic grid barrier state (never reset -> deterministic across graph replays)
__device__ unsigned g_cnt = 0;
__device__ unsigned g_rel = 0;

__device__ __forceinline__ void grid_barrier_dev(unsigned total)
{
    __syncthreads();
    if (threadIdx.x == 0) {
        __threadfence();
        unsigned my = atomicAdd(&g_cnt, 1u);
        if ((my % total) == total - 1u) {
            atomicAdd(&g_rel, 1u);
        } else {
            unsigned need = my / total + 1u;
            while (*((volatile unsigned*)&g_rel) < need) { }
        }
    }
    __syncthreads();
}

// -------- K0: build Wt (S row-major) and Wit (Wi transpose) --------
__global__ void k_prep(const float* __restrict__ Whh, const float* __restrict__ Wi)
{
    int idx = blockIdx.x * blockDim.x + threadIdx.x;   // over H*H
    if (idx < H_*H_) {
        int j = idx / H_, k = idx % H_;
        g_Wt[k*H_ + j] = Whh[idx];
    }
    if (idx < H_*I_) {
        int j = idx / I_, i = idx % I_;
        g_Wit[i*H_ + j] = Wi[idx];
    }
}

// ---------------------------------------------------------------------------
// gemm_k: C = A[M,K] @ B[K,Nn]   (both row-major, C pitch = Nn)
// tile 128m x 64n, BK=16, 256 threads, per-thread 8m x 4n scalar FFMA.
// MODE 0: plain store (matrix squaring)
// MODE 1: RNN projection epilogue (q shift + bias + initial)
// ---------------------------------------------------------------------------
template<int MODE>
__global__ void __launch_bounds__(256, 2)
gemm_k(const float* __restrict__ A, const float* __restrict__ B,
       float* __restrict__ Cc, int M, int K, int Nn,
       const float* __restrict__ bias, const float* __restrict__ initial)
{
    __shared__ __align__(16) float As[16][136];  // [k][m]
    __shared__ __align__(16) float Bs[16][64];   // [k][n]

    const int tid = threadIdx.x;
    const int bm = blockIdx.y * 128;
    const int bn = blockIdx.x * 64;
    const int tx = tid & 15;        // n group: bn + tx*4
    const int ty = tid >> 4;        // m group: bm + ty*8

    const int arow = tid >> 1;
    const int akof = (tid & 1) * 8;
    const int brow = tid >> 4;
    const int bcol = (tid & 15) * 4;

    float acc[8][4];
#pragma unroll
    for (int i = 0; i < 8; ++i)
#pragma unroll
        for (int jj = 0; jj < 4; ++jj) acc[i][jj] = 0.f;

    for (int kt = 0; kt < K; kt += 16) {
        const float* Ab = A + (size_t)(bm + arow) * K + kt + akof;
        float4 a0 = *(const float4*)&Ab[0];
        float4 a1 = *(const float4*)&Ab[4];
        As[akof+0][arow] = a0.x; As[akof+1][arow] = a0.y;
        As[akof+2][arow] = a0.z; As[akof+3][arow] = a0.w;
        As[akof+4][arow] = a1.x; As[akof+5][arow] = a1.y;
        As[akof+6][arow] = a1.z; As[akof+7][arow] = a1.w;
        *(float4*)&Bs[brow][bcol] = *(const float4*)&B[(size_t)(kt + brow) * Nn + bn + bcol];
        __syncthreads();

#pragma unroll
        for (int k = 0; k < 16; ++k) {
            float4 av0 = *(const float4*)&As[k][ty*8];
            float4 av1 = *(const float4*)&As[k][ty*8 + 4];
            float4 bv  = *(const float4*)&Bs[k][tx*4];
            float am[8] = {av0.x,av0.y,av0.z,av0.w, av1.x,av1.y,av1.z,av1.w};
            float bb[4] = {bv.x,bv.y,bv.z,bv.w};
#pragma unroll
            for (int i = 0; i < 8; ++i)
#pragma unroll
                for (int jj = 0; jj < 4; ++jj)
                    acc[i][jj] = fmaf(am[i], bb[jj], acc[i][jj]);
        }
        __syncthreads();
    }

    if (MODE == 0) {
#pragma unroll
        for (int i = 0; i < 8; ++i) {
            int m = bm + ty*8 + i;
            *(float4*)&Cc[(size_t)m * Nn + bn + tx*4]
                = make_float4(acc[i][0], acc[i][1], acc[i][2], acc[i][3]);
        }
    } else {
        float4 bv = *(const float4*)&bias[bn + tx*4];
#pragma unroll
        for (int i = 0; i < 8; ++i) {
            int r = bm + ty*8 + i;
            int s = r & (T_ - 1);
            int n = r >> 12;
            float4 v = make_float4(acc[i][0]+bv.x, acc[i][1]+bv.y,
                                   acc[i][2]+bv.z, acc[i][3]+bv.w);
            if (s < T_ - 1)
                *(float4*)&Cc[((size_t)n*T_ + s + 1)*H_ + bn + tx*4] = v;
            if (s == 0) {
                float4 iv = *(const float4*)&initial[(size_t)n*H_ + bn + tx*4];
                *(float4*)&Cc[((size_t)n*T_)*H_ + bn + tx*4]
                    = make_float4(v.x+iv.x, v.y+iv.y, v.z+iv.z, v.w+iv.w);
            }
        }
    }
}

// -------- K2: local scan per chunk (carry-in = 0), in place over q --------
// EXACT round-1 version (Wt layout, 4 coalesced scalar weight loads, unroll 4).
__global__ void __launch_bounds__(512, 1)
k_local(const float* __restrict__ Wt, float* __restrict__ q, float* __restrict__ lend)
{
    __shared__ __align__(16) float hs[N_][H_];
    const int c = blockIdx.x;
    const int j = threadIdx.x;
    const int t0 = c * L_;

    float acc[N_];
#pragma unroll
    for (int n = 0; n < N_; ++n) {
        acc[n] = q[((size_t)n*T_ + t0)*H_ + j];   // l[t0] = q[t0]
        hs[n][j] = acc[n];
    }
    __syncthreads();

    for (int s = 1; s < L_; ++s) {
        const size_t t = (size_t)t0 + s;
#pragma unroll
        for (int n = 0; n < N_; ++n)
            acc[n] = q[((size_t)n*T_ + t)*H_ + j];
#pragma unroll 4
        for (int k4 = 0; k4 < H_/4; ++k4) {
            const int k = k4 * 4;
            float w0 = Wt[(k+0)*H_ + j];
            float w1 = Wt[(k+1)*H_ + j];
            float w2 = Wt[(k+2)*H_ + j];
            float w3 = Wt[(k+3)*H_ + j];
#pragma unroll
            for (int n = 0; n < N_; ++n) {
                float4 h = *(const float4*)&hs[n][k];
                acc[n] = fmaf(h.x, w0, acc[n]);
                acc[n] = fmaf(h.y, w1, acc[n]);
                acc[n] = fmaf(h.z, w2, acc[n]);
                acc[n] = fmaf(h.w, w3, acc[n]);
            }
        }
        __syncthreads();
#pragma unroll
        for (int n = 0; n < N_; ++n) {
            hs[n][j] = acc[n];
            q[((size_t)n*T_ + t)*H_ + j] = acc[n];
        }
        __syncthreads();
    }
#pragma unroll
    for (int n = 0; n < N_; ++n)
        lend[((size_t)c*N_ + n)*H_ + j] = acc[n];
}

// -------- K4: boundary scan (persistent, grid barrier) — round-1 version --------
// hb[0] = lend[0];  hb[c] = W^L @ hb[c-1] + lend[c];  ML = (W^L)^T row-major.
__global__ void __launch_bounds__(128, 1)
k_bscan(const float* __restrict__ ML, const float* __restrict__ lend, float* __restrict__ hb)
{
    const int b   = blockIdx.x;
    const int tid = threadIdx.x;
    const unsigned total = gridDim.x;          // 64
    const int n = tid >> 3;                    // 0..15
    const int j = b * 8 + (tid & 7);           // 0..511

    {
        int idx = b * 128 + tid;               // 64*128 = 8192 = N*H
        __stcg(&hb[idx], lend[idx]);
    }
    grid_barrier_dev(total);

    for (int c = 1; c < C_; ++c) {
        const float4* hp4 = (const float4*)(hb + (size_t)(c-1)*N_*H_ + (size_t)n*H_);
        float a0 = 0.f, a1 = 0.f, a2 = 0.f, a3 = 0.f;
#pragma unroll 4
        for (int k4 = 0; k4 < H_/4; ++k4) {
            float4 h = __ldcg(&hp4[k4]);       // peer-CTA data: L2 path
            const int k = k4 * 4;
            a0 = fmaf(h.x, ML[(size_t)(k+0)*H_ + j], a0);
            a1 = fmaf(h.y, ML[(size_t)(k+1)*H_ + j], a1);
            a2 = fmaf(h.z, ML[(size_t)(k+2)*H_ + j], a2);
            a3 = fmaf(h.w, ML[(size_t)(k+3)*H_ + j], a3);
        }
        float acc = lend[(size_t)c*N_*H_ + (size_t)n*H_ + j] + ((a0 + a1) + (a2 + a3));
        __stcg(&hb[(size_t)c*N_*H_ + (size_t)n*H_ + j], acc);
        grid_barrier_dev(total);
    }
}

// -------- K5: correction pass per chunk — round-1 version --------
__global__ void __launch_bounds__(512, 1)
k_corr(const float* __restrict__ Wt, const float* __restrict__ hb,
       float* __restrict__ out0, float* __restrict__ out1, int dup)
{
    const int c = blockIdx.x;
    const int j = threadIdx.x;

    if (c == 0) {   // chunk 0: local state IS the answer; just mirror to out1
        if (dup) {
            for (int s = 0; s < L_; ++s) {
#pragma unroll
                for (int n = 0; n < N_; ++n) {
                    size_t idx = ((size_t)n*T_ + s)*H_ + j;
                    out1[idx] = out0[idx];
                }
            }
        }
        return;
    }

    __shared__ __align__(16) float ds[N_][H_];
    const int t0 = c * L_;
#pragma unroll
    for (int n = 0; n < N_; ++n)
        ds[n][j] = hb[((size_t)(c-1)*N_ + n)*H_ + j];
    __syncthreads();

    for (int s = 0; s < L_; ++s) {
        const size_t t = (size_t)t0 + s;
        float acc[N_];
#pragma unroll
        for (int n = 0; n < N_; ++n) acc[n] = 0.f;
#pragma unroll 4
        for (int k4 = 0; k4 < H_/4; ++k4) {
            const int k = k4 * 4;
            float w0 = Wt[(k+0)*H_ + j];
            float w1 = Wt[(k+1)*H_ + j];
            float w2 = Wt[(k+2)*H_ + j];
            float w3 = Wt[(k+3)*H_ + j];
#pragma unroll
            for (int n = 0; n < N_; ++n) {
                float4 h = *(const float4*)&ds[n][k];
                acc[n] = fmaf(h.x, w0, acc[n]);
                acc[n] = fmaf(h.y, w1, acc[n]);
                acc[n] = fmaf(h.z, w2, acc[n]);
                acc[n] = fmaf(h.w, w3, acc[n]);
            }
        }
        __syncthreads();
#pragma unroll
        for (int n = 0; n < N_; ++n) {
            ds[n][j] = acc[n];
            size_t idx = ((size_t)n*T_ + t)*H_ + j;
            float v = out0[idx] + acc[n];
            out0[idx] = v;
            if (dup) out1[idx] = v;
        }
        __syncthreads();
    }
}

// ----------------------------------------------------------------------------
extern "C" void kernel_launch(void* const* d_in, const int* in_sizes, int n_in,
                              void* d_out, int out_size)
{
    const float *x = nullptr, *initial = nullptr, *Wi = nullptr, *bi = nullptr, *Whh = nullptr;
    for (int i = 0; i < n_in; ++i) {
        switch (in_sizes[i]) {
            case N_*T_*I_: x       = (const float*)d_in[i]; break;
            case N_*H_:    initial = (const float*)d_in[i]; break;
            case H_*I_:    Wi      = (const float*)d_in[i]; break;
            case H_:       bi      = (const float*)d_in[i]; break;
            case H_*H_:    Whh     = (const float*)d_in[i]; break;
        }
    }
    if (!x       && n_in > 0) x       = (const float*)d_in[0];
    if (!initial && n_in > 1) initial = (const float*)d_in[1];
    if (!Wi      && n_in > 2) Wi      = (const float*)d_in[2];
    if (!bi      && n_in > 3) bi      = (const float*)d_in[3];
    if (!Whh     && n_in > 4) Whh     = (const float*)d_in[4];

    float* out0 = (float*)d_out;
    const size_t NTH = (size_t)N_ * T_ * H_;
    int dup = ((size_t)out_size >= 2 * NTH) ? 1 : 0;
    float* out1 = out0 + NTH;

    float *Wt, *Wit, *P0, *P1, *lend, *hb;
    cudaGetSymbolAddress((void**)&Wt,   g_Wt);
    cudaGetSymbolAddress((void**)&Wit,  g_Wit);
    cudaGetSymbolAddress((void**)&P0,   g_P0);
    cudaGetSymbolAddress((void**)&P1,   g_P1);
    cudaGetSymbolAddress((void**)&lend, g_lend);
    cudaGetSymbolAddress((void**)&hb,   g_hb);

    dim3 gs(H_/64, H_/128);        // squaring grid (8, 4)

    // #1: weight layouts
    k_prep<<<(H_*H_ + 255)/256, 256>>>(Whh, Wi);

    // #2: projection q into out0:  q = x @ Wit  (+ shift/bias/initial epilogue)
    {
        dim3 g(H_/64, (N_*T_)/128);   // (8, 512)
        gemm_k<1><<<g, 256>>>(x, Wit, out0, N_*T_, I_, H_, bi, initial);
    }

    // #3-4: first two squarings of S = Whh^T (row-major chain)
    gemm_k<0><<<gs, 256>>>(Wt, Wt, P0, H_, H_, H_, nullptr, nullptr); // S^2
    gemm_k<0><<<gs, 256>>>(P0, P0, P1, H_, H_, H_, nullptr, nullptr); // S^4

    // #5 (ncu -s 5 -c 1 lands here per r4 offset evidence): local scan
    k_local<<<C_, 512>>>(Wt, out0, lend);

    // #6-8: remaining squarings -> P0 = S^32 = (Whh^32)^T row-major
    gemm_k<0><<<gs, 256>>>(P1, P1, P0, H_, H_, H_, nullptr, nullptr); // S^8
    gemm_k<0><<<gs, 256>>>(P0, P0, P1, H_, H_, H_, nullptr, nullptr); // S^16
    gemm_k<0><<<gs, 256>>>(P1, P1, P0, H_, H_, H_, nullptr, nullptr); // S^32

    // #9: boundary scan (persistent kernel, 64 CTAs, grid barrier)
    k_bscan<<<64, 128>>>(P0, lend, hb);

    // #10: correction + finalize (+ duplicate output)
    k_corr<<<C_, 512>>>(Wt, hb, out0, out1, dup);
}